// round 10
// baseline (speedup 1.0000x reference)
#include <cuda_runtime.h>
#include <math.h>
#include <cstddef>
#include <cstdint>

// ---------------------------------------------------------------------------
// 3-layer bidirectional GRU.  T=256, B=64, IN=2048 (=2H), H=1024, L=3, D=2
// Per layer: init_layer + gemm_gx (tf32 mma.sync, RN-rounded, ldmatrix
// fragment loads) + gru_layer (persistent, whh SMEM-resident, FFMA2).
// ---------------------------------------------------------------------------

#define T_STEPS 256
#define BATCH   64
#define HID     1024
#define GATES   3072
#define NW      6144
#define KW      2048
#define MW      16384

#define LT_THREADS 384
#define BK      64
#define WPITCH  52
#define HPITCH  68
#define GPITCH  52

__device__ float g_gx  [(size_t)MW * NW];
__device__ float g_bufA[(size_t)T_STEPS * BATCH * 2048];
__device__ float g_bufB[(size_t)T_STEPS * BATCH * 2048];
__device__ float g_hbuf[2 * 2 * HID * BATCH];   // [dir][parity][j][b] transposed
__device__ unsigned g_bar;

typedef unsigned long long ull;

__device__ __forceinline__ ull fma2(ull a, ull b, ull c) {
    ull d;
    asm("fma.rn.f32x2 %0, %1, %2, %3;" : "=l"(d) : "l"(a), "l"(b), "l"(c));
    return d;
}
__device__ __forceinline__ ull dup2(float x) {
    ull d;
    asm("mov.b64 %0, {%1, %1};" : "=l"(d) : "f"(x));
    return d;
}
__device__ __forceinline__ float2 unpack2(ull v) {
    float2 f;
    asm("mov.b64 {%0, %1}, %2;" : "=f"(f.x), "=f"(f.y) : "l"(v));
    return f;
}
__device__ __forceinline__ float4 ldcg4(const float4* p) {
    float4 v;
    asm volatile("ld.global.cg.v4.f32 {%0,%1,%2,%3}, [%4];"
                 : "=f"(v.x), "=f"(v.y), "=f"(v.z), "=f"(v.w) : "l"(p));
    return v;
}
__device__ __forceinline__ float ldcg1(const float* p) {
    float v;
    asm volatile("ld.global.cg.f32 %0, [%1];" : "=f"(v) : "l"(p));
    return v;
}
__device__ __forceinline__ uint32_t tf32rn(float x) {   // round-to-nearest tf32
    uint32_t r;
    asm("cvt.rna.tf32.f32 %0, %1;" : "=r"(r) : "f"(x));
    return r;
}
__device__ __forceinline__ uint32_t smem_u32(const void* p) {
    uint32_t a;
    asm("{ .reg .u64 t; cvta.to.shared.u64 t, %1; cvt.u32.u64 %0, t; }"
        : "=r"(a) : "l"(p));
    return a;
}
__device__ __forceinline__ void ldsm4(uint32_t r[4], uint32_t addr) {
    asm volatile("ldmatrix.sync.aligned.m8n8.x4.shared.b16 {%0,%1,%2,%3}, [%4];"
                 : "=r"(r[0]), "=r"(r[1]), "=r"(r[2]), "=r"(r[3]) : "r"(addr));
}
// tf32 warp MMA: D(16x8) += A(16x8,row) * B(8x8,col).
__device__ __forceinline__ void mma_tf32(float d[4], const uint32_t a[4],
                                         uint32_t b0, uint32_t b1) {
    asm("mma.sync.aligned.m16n8k8.row.col.f32.tf32.tf32.f32 "
        "{%0,%1,%2,%3}, {%4,%5,%6,%7}, {%8,%9}, {%0,%1,%2,%3};"
        : "+f"(d[0]), "+f"(d[1]), "+f"(d[2]), "+f"(d[3])
        : "r"(a[0]), "r"(a[1]), "r"(a[2]), "r"(a[3]), "r"(b0), "r"(b1));
}

// ---------------------------------------------------------------------------
// Kernel 0: per-layer init. Transpose h0[l] -> hbufT parity-1; zero g_bar.
// ---------------------------------------------------------------------------
__global__ __launch_bounds__(256) void init_layer(const float* __restrict__ h0_l,
                                                  float* __restrict__ hbuf)
{
    int idx = blockIdx.x * 256 + threadIdx.x;      // [0, 131072)
    if (idx == 0) g_bar = 0u;
    int d = idx >> 16;
    int r = idx & 65535;
    int j = r & (HID - 1);
    int b = r >> 10;
    hbuf[(size_t)(d * 2 + 1) * (HID * BATCH) + j * BATCH + b] =
        h0_l[(size_t)d * (BATCH * HID) + (size_t)b * HID + j];
}

// ---------------------------------------------------------------------------
// Kernel 1 (R10): gx GEMM, tf32 mma.sync + ldmatrix + RN rounding.
//   CTA 128x128xBK32, 256 thr = 8 warps (2m x 4n), warp tile 64x32,
//   per-warp 4x4 frags of m16n8k8. Pitch GP=36 floats (144B = 9x16B):
//   conflict-free LDSM.
// ---------------------------------------------------------------------------
#define GP 36
__global__ __launch_bounds__(256) void gemm_gx(
    const float* __restrict__ A, const float* __restrict__ W,
    const float* __restrict__ bias, float* __restrict__ C)
{
    __shared__ __align__(16) float As[128][GP];
    __shared__ __align__(16) float Ws[128][GP];

    const int tid  = threadIdx.x;
    const int lane = tid & 31;
    const int wid  = tid >> 5;
    const int wm   = wid & 1;          // 2 warps in m
    const int wn   = wid >> 1;         // 4 warps in n
    const int g    = lane >> 2;        // mma group id 0..7
    const int c    = lane & 3;         // thread-in-group 0..3
    const int n0   = blockIdx.x * 128;
    const int m0   = blockIdx.y * 128;

    // ldmatrix per-lane source addressing: seg = lane>>3, r8 = lane&7
    const int seg = lane >> 3;
    const int r8  = lane & 7;
    const uint32_t a_base = smem_u32(As)
        + (uint32_t)((wm * 64 + r8 + ((seg & 1) << 3)) * GP * 4)
        + (uint32_t)((seg & 2) << 3);              // +0 or +16 bytes
    const uint32_t b_base = smem_u32(Ws)
        + (uint32_t)((wn * 32 + r8 + ((seg & 1) << 3)) * GP * 4)
        + (uint32_t)((seg & 2) << 3);

    // staging: 1024 float4 per operand tile / 256 thr = 4 each
    const int srow = tid >> 3;          // 0..31
    const int skq  = (tid & 7) * 4;     // 0..28

    const float* Ap[4];
    const float* Wp[4];
#pragma unroll
    for (int i = 0; i < 4; i++) {
        Ap[i] = A + (size_t)(m0 + srow + 32 * i) * KW + skq;
        Wp[i] = W + (size_t)(n0 + srow + 32 * i) * KW + skq;
    }

    float acc[4][4][4];
#pragma unroll
    for (int mi = 0; mi < 4; mi++)
#pragma unroll
        for (int nj = 0; nj < 4; nj++)
#pragma unroll
            for (int q = 0; q < 4; q++) acc[mi][nj][q] = 0.f;

    float4 va[4], vw[4];
#pragma unroll
    for (int i = 0; i < 4; i++) { va[i] = *(const float4*)Ap[i];
                                  vw[i] = *(const float4*)Wp[i]; }

    for (int k0 = 0; k0 < KW; k0 += 32) {
        __syncthreads();
#pragma unroll
        for (int i = 0; i < 4; i++) {   // store RN-rounded tf32 bits
            uint4 ua = make_uint4(tf32rn(va[i].x), tf32rn(va[i].y),
                                  tf32rn(va[i].z), tf32rn(va[i].w));
            uint4 uw = make_uint4(tf32rn(vw[i].x), tf32rn(vw[i].y),
                                  tf32rn(vw[i].z), tf32rn(vw[i].w));
            *(uint4*)&As[srow + 32 * i][skq] = ua;
            *(uint4*)&Ws[srow + 32 * i][skq] = uw;
        }
        __syncthreads();

        if (k0 + 32 < KW) {
#pragma unroll
            for (int i = 0; i < 4; i++) {
                va[i] = *(const float4*)(Ap[i] + k0 + 32);
                vw[i] = *(const float4*)(Wp[i] + k0 + 32);
            }
        }

#pragma unroll
        for (int ks = 0; ks < 4; ks++) {
            uint32_t a[4][4], bb[2][4];
#pragma unroll
            for (int mi = 0; mi < 4; mi++)
                ldsm4(a[mi], a_base + (uint32_t)(mi * 16 * GP * 4 + ks * 32));
#pragma unroll
            for (int p = 0; p < 2; p++)
                ldsm4(bb[p], b_base + (uint32_t)(p * 16 * GP * 4 + ks * 32));
            // bb[p] = { b[2p][0], b[2p+1][0], b[2p][1], b[2p+1][1] }
#pragma unroll
            for (int mi = 0; mi < 4; mi++)
#pragma unroll
                for (int nj = 0; nj < 4; nj++)
                    mma_tf32(acc[mi][nj], a[mi],
                             bb[nj >> 1][nj & 1], bb[nj >> 1][2 + (nj & 1)]);
        }
    }

    // epilogue: per (mi,nj): rows mbase+mi*16+g(+8), cols nbase+nj*8+2c(,+1)
#pragma unroll
    for (int nj = 0; nj < 4; nj++) {
        const int col = n0 + wn * 32 + nj * 8 + 2 * c;
        const float b0 = bias[col];
        const float b1 = bias[col + 1];
#pragma unroll
        for (int mi = 0; mi < 4; mi++) {
            const int row = m0 + wm * 64 + mi * 16 + g;
            float* p0 = C + (size_t)row * NW + col;
            float* p1 = C + (size_t)(row + 8) * NW + col;
            *(float2*)p0 = make_float2(acc[mi][nj][0] + b0, acc[mi][nj][1] + b1);
            *(float2*)p1 = make_float2(acc[mi][nj][2] + b0, acc[mi][nj][3] + b1);
        }
    }
}

// ---------------------------------------------------------------------------
// Kernel 2: persistent per-layer GRU (unchanged from R9).
// 128 CTAs: d=bx>>6, jbase=(bx&63)*16. wsT[1024][52] resident whh slice;
// hs[64][68] h tile (overlaid by ghf); 4-way K-split, acc[4][4], FFMA2.
// ---------------------------------------------------------------------------
#define SM_WS_BYTES  (HID * WPITCH * 4)
#define SM_HS_BYTES  (BK * HPITCH * 4)
#define SM_TOTAL     (SM_WS_BYTES + SM_HS_BYTES + 256)

__global__ __launch_bounds__(LT_THREADS, 1) void gru_layer(
    const float* __restrict__ gx, const float* __restrict__ whh_l,
    const float* __restrict__ bhh_l, float* __restrict__ hbuf,
    float* __restrict__ yout, float* __restrict__ hn_out)
{
    extern __shared__ char smraw[];
    float* wsT = (float*)smraw;                          // [1024][WPITCH]
    float* hs  = (float*)(smraw + SM_WS_BYTES);          // [64][HPITCH]
    float* ghf = hs;                                     // overlay [64][GPITCH]
    float* bsm = (float*)(smraw + SM_WS_BYTES + SM_HS_BYTES);

    const int tid = threadIdx.x;
    const int d     = blockIdx.x >> 6;
    const int jbase = (blockIdx.x & 63) << 4;
    const int g    = tid / 96;        // K-split group 0..3
    const int r    = tid - g * 96;
    const int c0   = (r % 12) * 4;    // 4 cols
    const int b0   = (r / 12) * 8;    // 8 batches (4 pairs)

    const float* whh = whh_l + (size_t)d * GATES * HID;
    const float* bhh = bhh_l + d * GATES;

#pragma unroll 4
    for (int it = 0; it < 32; it++) {
        int f4i = tid + it * 384;
        int cc  = f4i >> 8;
        int kq  = (f4i & 255) << 2;
        int grow = ((cc >> 4) << 10) + jbase + (cc & 15);
        float4 v = *(const float4*)(whh + (size_t)grow * HID + kq);
        wsT[(kq + 0) * WPITCH + cc] = v.x;
        wsT[(kq + 1) * WPITCH + cc] = v.y;
        wsT[(kq + 2) * WPITCH + cc] = v.z;
        wsT[(kq + 3) * WPITCH + cc] = v.w;
    }
    if (tid < 48)
        bsm[tid] = bhh[((tid >> 4) << 10) + jbase + (tid & 15)];
    __syncthreads();

    for (int t = 0; t < T_STEPS; t++) {
        const float* h_in  = hbuf + (size_t)(d*2 + ((t&1)^1)) * (HID*BATCH);
        float*       h_out = hbuf + (size_t)(d*2 + (t&1))     * (HID*BATCH);
        const int tt = d ? (T_STEPS - 1 - t) : t;
        const float* gxp = gx + (size_t)tt * BATCH * NW + (size_t)d * GATES;

        float pgr[3], pgz[3], pgn[3], php[3];
#pragma unroll
        for (int e = 0; e < 3; e++) {
            int idx = tid + 384 * e;
            pgr[e] = pgz[e] = pgn[e] = php[e] = 0.f;
            if (idx < 1024) {
                int b = idx >> 4, jj = idx & 15, j = jbase + jj;
                const float* gxb = gxp + (size_t)b * NW;
                pgr[e] = __ldg(gxb + j);
                pgz[e] = __ldg(gxb + HID + j);
                pgn[e] = __ldg(gxb + 2*HID + j);
                php[e] = ldcg1(h_in + (size_t)j * BATCH + b);
            }
        }

        ull acc[4][4];
#pragma unroll
        for (int cc = 0; cc < 4; cc++)
#pragma unroll
            for (int bp = 0; bp < 4; bp++) acc[cc][bp] = 0ULL;

        const float4* hsrc = (const float4*)h_in;
        float4 hv0 = ldcg4(hsrc + tid);
        float4 hv1 = ldcg4(hsrc + 384 + tid);
        float4 hv2 = make_float4(0.f,0.f,0.f,0.f);
        if (tid < 256) hv2 = ldcg4(hsrc + 768 + tid);

        for (int blk = 0; blk < HID / BK; blk++) {
            __syncthreads();
            {
                int i0 = tid;
                *(float4*)&hs[(i0 >> 4) * HPITCH + ((i0 & 15) << 2)] = hv0;
                int i1 = tid + 384;
                *(float4*)&hs[(i1 >> 4) * HPITCH + ((i1 & 15) << 2)] = hv1;
                if (tid < 256) {
                    int i2 = tid + 768;
                    *(float4*)&hs[(i2 >> 4) * HPITCH + ((i2 & 15) << 2)] = hv2;
                }
            }
            __syncthreads();

            if (blk < HID / BK - 1) {
                const float4* hn = hsrc + (blk + 1) * (BK * BATCH / 4);
                hv0 = ldcg4(hn + tid);
                hv1 = ldcg4(hn + 384 + tid);
                if (tid < 256) hv2 = ldcg4(hn + 768 + tid);
            }

            const int kbase = g * 16;
#pragma unroll
            for (int kk = 0; kk < 16; kk++) {
                const int krow = kbase + kk;
                const float4 wv =
                    *(const float4*)(wsT + (size_t)(blk * BK + krow) * WPITCH + c0);
                ull ww0 = dup2(wv.x), ww1 = dup2(wv.y);
                ull ww2 = dup2(wv.z), ww3 = dup2(wv.w);
                const float* hr = hs + krow * HPITCH + b0;
                ulonglong2 hA = *(const ulonglong2*)hr;
                ulonglong2 hB = *(const ulonglong2*)(hr + 4);
                acc[0][0] = fma2(hA.x, ww0, acc[0][0]);
                acc[1][0] = fma2(hA.x, ww1, acc[1][0]);
                acc[2][0] = fma2(hA.x, ww2, acc[2][0]);
                acc[3][0] = fma2(hA.x, ww3, acc[3][0]);
                acc[0][1] = fma2(hA.y, ww0, acc[0][1]);
                acc[1][1] = fma2(hA.y, ww1, acc[1][1]);
                acc[2][1] = fma2(hA.y, ww2, acc[2][1]);
                acc[3][1] = fma2(hA.y, ww3, acc[3][1]);
                acc[0][2] = fma2(hB.x, ww0, acc[0][2]);
                acc[1][2] = fma2(hB.x, ww1, acc[1][2]);
                acc[2][2] = fma2(hB.x, ww2, acc[2][2]);
                acc[3][2] = fma2(hB.x, ww3, acc[3][2]);
                acc[0][3] = fma2(hB.y, ww0, acc[0][3]);
                acc[1][3] = fma2(hB.y, ww1, acc[1][3]);
                acc[2][3] = fma2(hB.y, ww2, acc[2][3]);
                acc[3][3] = fma2(hB.y, ww3, acc[3][3]);
            }
        }

        __syncthreads();
#pragma unroll 1
        for (int gr = 0; gr < 4; gr++) {
            if (g == gr) {
#pragma unroll
                for (int bb = 0; bb < 8; bb++) {
                    float o[4];
#pragma unroll
                    for (int cc = 0; cc < 4; cc++) {
                        float2 f = unpack2(acc[cc][bb >> 1]);
                        o[cc] = (bb & 1) ? f.y : f.x;
                    }
                    float* gp = ghf + (b0 + bb) * GPITCH + c0;
                    if (gr == 0) {
                        *(float4*)gp = make_float4(o[0], o[1], o[2], o[3]);
                    } else {
                        float4 p = *(float4*)gp;
                        *(float4*)gp = make_float4(p.x + o[0], p.y + o[1],
                                                   p.z + o[2], p.w + o[3]);
                    }
                }
            }
            __syncthreads();
        }

#pragma unroll
        for (int e = 0; e < 3; e++) {
            int idx = tid + 384 * e;
            if (idx < 1024) {
                int b = idx >> 4, jj = idx & 15, j = jbase + jj;
                float gr = ghf[b * GPITCH + jj];
                float gz = ghf[b * GPITCH + 16 + jj];
                float gn = ghf[b * GPITCH + 32 + jj];
                float rg = 1.f / (1.f + expf(-(pgr[e] + gr + bsm[jj])));
                float zg = 1.f / (1.f + expf(-(pgz[e] + gz + bsm[16 + jj])));
                float ng = tanhf(pgn[e] + rg * (gn + bsm[32 + jj]));
                float h  = ng + zg * (php[e] - ng);
                h_out[(size_t)j * BATCH + b] = h;
                if (yout)
                    yout[((size_t)tt * BATCH + b) * 2048 + (size_t)d * HID + j] = h;
                if (t == T_STEPS - 1)
                    hn_out[(size_t)d * (BATCH*HID) + (size_t)b * HID + j] = h;
            }
        }

        if (t < T_STEPS - 1) {
            __syncthreads();
            if (tid == 0) {
                __threadfence();
                atomicAdd(&g_bar, 1u);
                unsigned target = 128u * (unsigned)(t + 1);
                unsigned v;
                do {
                    asm volatile("ld.acquire.gpu.global.u32 %0, [%1];"
                                 : "=r"(v) : "l"(&g_bar) : "memory");
                } while (v < target);
            }
            __syncthreads();
        }
    }
}

// ---------------------------------------------------------------------------
// Host
// ---------------------------------------------------------------------------
namespace {
struct EagerLoad {
    EagerLoad() {
        void* p;
        cudaGetSymbolAddress(&p, g_gx);
        cudaGetSymbolAddress(&p, g_bufA);
        cudaGetSymbolAddress(&p, g_bufB);
        cudaGetSymbolAddress(&p, g_hbuf);
        cudaGetSymbolAddress(&p, g_bar);
        cudaFuncSetAttribute(gru_layer,
                             cudaFuncAttributeMaxDynamicSharedMemorySize,
                             SM_TOTAL);
    }
} s_eager_load;
}

extern "C" void kernel_launch(void* const* d_in, const int* in_sizes, int n_in,
                              void* d_out, int out_size)
{
    const float* x    = (const float*)d_in[0];
    const float* h0   = (const float*)d_in[1];
    const float* w_ih = (const float*)d_in[2];
    const float* w_hh = (const float*)d_in[3];
    const float* b_ih = (const float*)d_in[4];
    const float* b_hh = (const float*)d_in[5];
    float* out = (float*)d_out;
    (void)in_sizes; (void)n_in; (void)out_size;

    float *gx, *bufA, *bufB, *hbuf;
    cudaGetSymbolAddress((void**)&gx,   g_gx);
    cudaGetSymbolAddress((void**)&bufA, g_bufA);
    cudaGetSymbolAddress((void**)&bufB, g_bufB);
    cudaGetSymbolAddress((void**)&hbuf, g_hbuf);

    dim3 ggrid(NW / 128, MW / 128);   // (48, 128)

    for (int l = 0; l < 3; l++) {
        const float* in = (l == 0) ? x : ((l == 1) ? bufA : bufB);
        float* yout     = (l == 0) ? bufA : ((l == 1) ? bufB : nullptr);

        init_layer<<<512, 256>>>(h0 + (size_t)l * 2 * BATCH * HID, hbuf);

        gemm_gx<<<ggrid, 256>>>(in, w_ih + (size_t)l * NW * KW,
                                b_ih + (size_t)l * NW, gx);

        gru_layer<<<128, LT_THREADS, SM_TOTAL>>>(
            gx,
            w_hh + (size_t)l * 2 * GATES * HID,
            b_hh + (size_t)l * NW,
            hbuf, yout,
            out + (size_t)l * 2 * BATCH * HID);
    }
}